// round 6
// baseline (speedup 1.0000x reference)
#include <cuda_runtime.h>
#include <cuda_bf16.h>
#include <math.h>

#define NN 100000
#define EE 1600000
#define HH 128
#define CC 40
#define BN_EPS 1e-5f
#define SCAN_BLK 1024
#define SCAN_NB ((NN + SCAN_BLK - 1) / SCAN_BLK)
#define LDP 136

// ---------------- scratch ----------------
__device__ float  g_h[(size_t)NN * HH];
__device__ float  g_agg[(size_t)NN * HH];
__device__ double g_stats[2 * HH];
__device__ float  g_scale[HH];
__device__ float  g_shift[HH];
__device__ int    g_degcnt[NN];
__device__ float  g_dinv[NN];
__device__ float  g_invdeg[NN];
__device__ int    g_rowptr[NN];
__device__ int    g_cursor[NN];
__device__ int    g_blksum[SCAN_NB];
__device__ int2   g_csr[EE];

// ---------------- helpers ----------------
__device__ __forceinline__ void fma4(float4& a, float s, float4 w) {
    a.x = fmaf(s, w.x, a.x);
    a.y = fmaf(s, w.y, a.y);
    a.z = fmaf(s, w.z, a.z);
    a.w = fmaf(s, w.w, a.w);
}

__device__ __forceinline__ float4 bn_relu4(float4 v, float4 sc, float4 sh) {
    float4 r;
    r.x = fmaxf(fmaf(v.x, sc.x, sh.x), 0.f);
    r.y = fmaxf(fmaf(v.y, sc.y, sh.y), 0.f);
    r.z = fmaxf(fmaf(v.z, sc.z, sh.z), 0.f);
    r.w = fmaxf(fmaf(v.w, sc.w, sh.w), 0.f);
    return r;
}

__device__ __forceinline__ unsigned smem_u32(const void* p) {
    return (unsigned)__cvta_generic_to_shared(p);
}

__device__ __forceinline__ void ldmatrix_x4(unsigned* r, unsigned addr) {
    asm volatile("ldmatrix.sync.aligned.m8n8.x4.shared.b16 {%0,%1,%2,%3}, [%4];"
                 : "=r"(r[0]), "=r"(r[1]), "=r"(r[2]), "=r"(r[3]) : "r"(addr));
}

__device__ __forceinline__ void ldmatrix_x2_t(unsigned* r, unsigned addr) {
    asm volatile("ldmatrix.sync.aligned.m8n8.x2.trans.shared.b16 {%0,%1}, [%2];"
                 : "=r"(r[0]), "=r"(r[1]) : "r"(addr));
}

__device__ __forceinline__ void mma_bf16(float* d, const unsigned* a, const unsigned* b) {
    asm volatile(
        "mma.sync.aligned.m16n8k16.row.col.f32.bf16.bf16.f32 "
        "{%0,%1,%2,%3}, {%4,%5,%6,%7}, {%8,%9}, {%0,%1,%2,%3};"
        : "+f"(d[0]), "+f"(d[1]), "+f"(d[2]), "+f"(d[3])
        : "r"(a[0]), "r"(a[1]), "r"(a[2]), "r"(a[3]), "r"(b[0]), "r"(b[1]));
}

// pack two floats into one u32 holding {bf16(hi(a)), bf16(hi(b))}, and the residual pair
__device__ __forceinline__ void split2(float a, float b, unsigned& hi2, unsigned& lo2) {
    __nv_bfloat16 ah = __float2bfloat16_rn(a);
    __nv_bfloat16 bh = __float2bfloat16_rn(b);
    __nv_bfloat16 al = __float2bfloat16_rn(a - __bfloat162float(ah));
    __nv_bfloat16 bl = __float2bfloat16_rn(b - __bfloat162float(bh));
    unsigned short ahu = *(unsigned short*)&ah;
    unsigned short bhu = *(unsigned short*)&bh;
    unsigned short alu = *(unsigned short*)&al;
    unsigned short blu = *(unsigned short*)&bl;
    hi2 = (unsigned)ahu | ((unsigned)bhu << 16);
    lo2 = (unsigned)alu | ((unsigned)blu << 16);
}

// ---------------- degree ----------------
__global__ void deg_count_kernel(const int* __restrict__ dst) {
    int e = blockIdx.x * blockDim.x + threadIdx.x;
    if (e < EE) atomicAdd(&g_degcnt[dst[e]], 1);
}

__global__ void deg_finish_kernel() {
    int i = blockIdx.x * blockDim.x + threadIdx.x;
    if (i < NN) {
        float f = (float)(g_degcnt[i] + 1);
        g_dinv[i]   = rsqrtf(f);
        g_invdeg[i] = 1.0f / f;
    }
}

// ---------------- exclusive scan ----------------
__global__ __launch_bounds__(SCAN_BLK) void scan1_kernel() {
    __shared__ int sm[SCAN_BLK];
    int i = blockIdx.x * SCAN_BLK + threadIdx.x;
    int v = (i < NN) ? g_degcnt[i] : 0;
    sm[threadIdx.x] = v;
    __syncthreads();
    for (int off = 1; off < SCAN_BLK; off <<= 1) {
        int t = (threadIdx.x >= off) ? sm[threadIdx.x - off] : 0;
        __syncthreads();
        sm[threadIdx.x] += t;
        __syncthreads();
    }
    if (i < NN) g_rowptr[i] = sm[threadIdx.x] - v;
    if (threadIdx.x == SCAN_BLK - 1) g_blksum[blockIdx.x] = sm[SCAN_BLK - 1];
}

__global__ void scan2_kernel() {
    __shared__ int sm[128];
    int v = (threadIdx.x < SCAN_NB) ? g_blksum[threadIdx.x] : 0;
    sm[threadIdx.x] = v;
    __syncthreads();
    for (int off = 1; off < 128; off <<= 1) {
        int t = (threadIdx.x >= off) ? sm[threadIdx.x - off] : 0;
        __syncthreads();
        sm[threadIdx.x] += t;
        __syncthreads();
    }
    if (threadIdx.x < SCAN_NB) g_blksum[threadIdx.x] = sm[threadIdx.x] - v;
}

__global__ void scan3_kernel() {
    int i = blockIdx.x * blockDim.x + threadIdx.x;
    if (i < NN) g_rowptr[i] += g_blksum[i >> 10];
}

// ---------------- CSR fill ----------------
__global__ void csr_fill_kernel(const int* __restrict__ src,
                                const int* __restrict__ dst) {
    int e = blockIdx.x * blockDim.x + threadIdx.x;
    if (e >= EE) return;
    int s = src[e], d = dst[e];
    int pos = g_rowptr[d] + atomicAdd(&g_cursor[d], 1);
    float w = g_dinv[s] * g_dinv[d];
    g_csr[pos] = make_int2(s, __float_as_int(w));
}

// ---------------- tensor-core GEMM [n,128]@[128,128], split-bf16 (3 MMA) ----------------
// 256 thr / 8 warps; block tile 128x128; warp tile 32x64.
template<bool BN>
__global__ __launch_bounds__(256) void gemm128_mma_kernel(
    const float* __restrict__ X, const float* __restrict__ W,
    float* __restrict__ Y, int nrows)
{
    extern __shared__ __align__(16) char smraw[];
    __nv_bfloat16* Whi = (__nv_bfloat16*)smraw;
    __nv_bfloat16* Wlo = Whi + HH * LDP;
    __nv_bfloat16* Xhi = Wlo + HH * LDP;
    __nv_bfloat16* Xlo = Xhi + HH * LDP;

    int tid  = threadIdx.x;
    int lane = tid & 31;
    int warp = tid >> 5;

    // fill W hi/lo (pairwise along n)
    for (int i = tid; i < HH * 64; i += 256) {
        int k = i >> 6;
        int n2 = i & 63;
        const float* wp = W + k * HH + n2 * 2;
        unsigned hi2, lo2;
        split2(wp[0], wp[1], hi2, lo2);
        *(unsigned*)(Whi + k * LDP + n2 * 2) = hi2;
        *(unsigned*)(Wlo + k * LDP + n2 * 2) = lo2;
    }

    // fill X hi/lo (fused BN+ReLU)
    int row0 = blockIdx.x * 128;
    for (int i = tid; i < 128 * 32; i += 256) {
        int r  = i >> 5;
        int c4 = i & 31;
        int row = row0 + r;
        float4 xv = make_float4(0.f, 0.f, 0.f, 0.f);
        if (row < nrows) xv = ((const float4*)X)[(size_t)row * 32 + c4];
        if (BN) {
            float4 sc = ((const float4*)g_scale)[c4];
            float4 sh = ((const float4*)g_shift)[c4];
            xv = bn_relu4(xv, sc, sh);
        }
        unsigned h01, l01, h23, l23;
        split2(xv.x, xv.y, h01, l01);
        split2(xv.z, xv.w, h23, l23);
        unsigned* ph = (unsigned*)(Xhi + r * LDP + c4 * 4);
        unsigned* pl = (unsigned*)(Xlo + r * LDP + c4 * 4);
        ph[0] = h01;
        ph[1] = h23;
        pl[0] = l01;
        pl[1] = l23;
    }
    __syncthreads();

    int wm = (warp & 3) * 32;
    int wn = (warp >> 2) * 64;

    float acc[2][8][4];
    for (int mt = 0; mt < 2; mt++) {
        for (int nt = 0; nt < 8; nt++) {
            acc[mt][nt][0] = 0.f;
            acc[mt][nt][1] = 0.f;
            acc[mt][nt][2] = 0.f;
            acc[mt][nt][3] = 0.f;
        }
    }

    int a_row = wm + (lane & 15);
    int a_col = (lane >> 4) << 3;
    int b_k   = (lane & 7) + (((lane >> 3) & 1) << 3);

    unsigned xhi_base = smem_u32(Xhi);
    unsigned xlo_base = smem_u32(Xlo);
    unsigned whi_base = smem_u32(Whi);
    unsigned wlo_base = smem_u32(Wlo);

#pragma unroll
    for (int k = 0; k < HH; k += 16) {
        unsigned Ah[2][4];
        unsigned Al[2][4];
#pragma unroll
        for (int mt = 0; mt < 2; mt++) {
            unsigned off = (unsigned)((a_row + mt * 16) * LDP + k + a_col) * 2u;
            ldmatrix_x4(Ah[mt], xhi_base + off);
            ldmatrix_x4(Al[mt], xlo_base + off);
        }
#pragma unroll
        for (int nt = 0; nt < 8; nt++) {
            unsigned off = (unsigned)((k + b_k) * LDP + wn + nt * 8) * 2u;
            unsigned Bh[2];
            unsigned Bl[2];
            ldmatrix_x2_t(Bh, whi_base + off);
            ldmatrix_x2_t(Bl, wlo_base + off);
#pragma unroll
            for (int mt = 0; mt < 2; mt++) {
                mma_bf16(acc[mt][nt], Ah[mt], Bh);
                mma_bf16(acc[mt][nt], Ah[mt], Bl);
                mma_bf16(acc[mt][nt], Al[mt], Bh);
            }
        }
    }

    int tq = lane >> 2;
    int tr = lane & 3;
#pragma unroll
    for (int mt = 0; mt < 2; mt++) {
#pragma unroll
        for (int nt = 0; nt < 8; nt++) {
            int r0 = row0 + wm + mt * 16 + tq;
            int c  = wn + nt * 8 + tr * 2;
            if (r0 < nrows) {
                float2 v;
                v.x = acc[mt][nt][0];
                v.y = acc[mt][nt][1];
                *(float2*)(Y + (size_t)r0 * HH + c) = v;
            }
            if (r0 + 8 < nrows) {
                float2 v;
                v.x = acc[mt][nt][2];
                v.y = acc[mt][nt][3];
                *(float2*)(Y + (size_t)(r0 + 8) * HH + c) = v;
            }
        }
    }
}

// ---------------- GEMM [n,128]@[128,40], fused BN+ReLU, SIMT fp32 ----------------
template<bool BN>
__global__ __launch_bounds__(256) void gemm40_kernel(
    const float* __restrict__ X, const float* __restrict__ W,
    float* __restrict__ Y, int nrows)
{
    extern __shared__ float smem[];
    float*  Ws = smem;
    float4* Xs = (float4*)(smem + HH * CC);

    int tid  = threadIdx.x;
    int lane = tid & 31;
    int warp = tid >> 5;

    for (int i = tid; i < HH * CC; i += 256) Ws[i] = W[i];
    __syncthreads();

    float4 sc, sh;
    if (BN) {
        sc = ((const float4*)g_scale)[lane];
        sh = ((const float4*)g_shift)[lane];
    }

    int base = blockIdx.x * 64 + warp * 8;
    const float4* X4 = (const float4*)X;
    float4* Xw = Xs + warp * 8 * 32;

#pragma unroll
    for (int r = 0; r < 8; r++) {
        int row = base + r;
        float4 xv = make_float4(0.f, 0.f, 0.f, 0.f);
        if (row < nrows) xv = X4[(size_t)row * 32 + lane];
        if (BN) xv = bn_relu4(xv, sc, sh);
        Xw[r * 32 + lane] = xv;
    }
    __syncwarp();

    float acca[8], accb[8];
#pragma unroll
    for (int r = 0; r < 8; r++) {
        acca[r] = 0.f;
        accb[r] = 0.f;
    }

    bool two = (lane < 8);

#pragma unroll 4
    for (int k0 = 0; k0 < 32; k0++) {
        float wa[4], wb[4];
#pragma unroll
        for (int j = 0; j < 4; j++) {
            wa[j] = Ws[(4 * k0 + j) * CC + lane];
            wb[j] = two ? Ws[(4 * k0 + j) * CC + 32 + lane] : 0.f;
        }
#pragma unroll
        for (int r = 0; r < 8; r++) {
            float4 xv = Xw[r * 32 + k0];
            acca[r] = fmaf(xv.x, wa[0], acca[r]);
            acca[r] = fmaf(xv.y, wa[1], acca[r]);
            acca[r] = fmaf(xv.z, wa[2], acca[r]);
            acca[r] = fmaf(xv.w, wa[3], acca[r]);
            accb[r] = fmaf(xv.x, wb[0], accb[r]);
            accb[r] = fmaf(xv.y, wb[1], accb[r]);
            accb[r] = fmaf(xv.z, wb[2], accb[r]);
            accb[r] = fmaf(xv.w, wb[3], accb[r]);
        }
    }

#pragma unroll
    for (int r = 0; r < 8; r++) {
        int row = base + r;
        if (row < nrows) {
            Y[(size_t)row * CC + lane] = acca[r];
            if (two) Y[(size_t)row * CC + 32 + lane] = accb[r];
        }
    }
}

// ---------------- fused CSR aggregation + self-loop + bias + BN stats ----------------
__global__ __launch_bounds__(256) void aggregate128_kernel(
    const float* __restrict__ h, float* __restrict__ agg,
    const float* __restrict__ bias)
{
    __shared__ float ssum[8 * HH];
    __shared__ float ssq[8 * HH];

    int lane = threadIdx.x & 31;
    int warp = threadIdx.x >> 5;
    int gw = blockIdx.x * 8 + warp;
    int nwarps = gridDim.x * 8;

    float4 bb = ((const float4*)bias)[lane];
    float4 ps  = make_float4(0.f, 0.f, 0.f, 0.f);
    float4 ps2 = make_float4(0.f, 0.f, 0.f, 0.f);

    const float4* h4 = (const float4*)h;

    for (int i = gw; i < NN; i += nwarps) {
        int start = g_rowptr[i];
        int end   = start + g_degcnt[i];
        float4 acc = make_float4(0.f, 0.f, 0.f, 0.f);

        int k = start;
        for (; k + 1 < end; k += 2) {
            int2 p0 = g_csr[k];
            int2 p1 = g_csr[k + 1];
            float4 v0 = __ldg(h4 + (size_t)p0.x * 32 + lane);
            float4 v1 = __ldg(h4 + (size_t)p1.x * 32 + lane);
            fma4(acc, __int_as_float(p0.y), v0);
            fma4(acc, __int_as_float(p1.y), v1);
        }
        if (k < end) {
            int2 p0 = g_csr[k];
            float4 v0 = __ldg(h4 + (size_t)p0.x * 32 + lane);
            fma4(acc, __int_as_float(p0.y), v0);
        }

        float4 hv = h4[(size_t)i * 32 + lane];
        float id = g_invdeg[i];
        acc.x = fmaf(id, hv.x, acc.x) + bb.x;
        acc.y = fmaf(id, hv.y, acc.y) + bb.y;
        acc.z = fmaf(id, hv.z, acc.z) + bb.z;
        acc.w = fmaf(id, hv.w, acc.w) + bb.w;
        ((float4*)agg)[(size_t)i * 32 + lane] = acc;

        ps.x += acc.x;
        ps.y += acc.y;
        ps.z += acc.z;
        ps.w += acc.w;
        ps2.x = fmaf(acc.x, acc.x, ps2.x);
        ps2.y = fmaf(acc.y, acc.y, ps2.y);
        ps2.z = fmaf(acc.z, acc.z, ps2.z);
        ps2.w = fmaf(acc.w, acc.w, ps2.w);
    }

    ((float4*)(ssum + warp * HH))[lane] = ps;
    ((float4*)(ssq  + warp * HH))[lane] = ps2;
    __syncthreads();
    if (threadIdx.x < HH) {
        int j = threadIdx.x;
        float ts = 0.f, ts2 = 0.f;
#pragma unroll
        for (int w = 0; w < 8; w++) {
            ts  += ssum[w * HH + j];
            ts2 += ssq[w * HH + j];
        }
        atomicAdd(&g_stats[j],      (double)ts);
        atomicAdd(&g_stats[HH + j], (double)ts2);
    }
}

__global__ void stats_final_kernel(const float* __restrict__ g,
                                   const float* __restrict__ be)
{
    int j = threadIdx.x;
    double mu  = g_stats[j] / (double)NN;
    double var = g_stats[HH + j] / (double)NN - mu * mu;
    float rs = rsqrtf((float)var + BN_EPS);
    float sc = g[j] * rs;
    g_scale[j] = sc;
    g_shift[j] = be[j] - (float)mu * sc;
}

// ---------------- layer-3: fused aggregation + bias + log_softmax ----------------
__global__ __launch_bounds__(256) void aggregate40_softmax_kernel(
    const float* __restrict__ h3, const float* __restrict__ b3,
    float* __restrict__ out)
{
    int lane = threadIdx.x & 31;
    int warp = threadIdx.x >> 5;
    int gw = blockIdx.x * 8 + warp;
    if (gw >= NN) return;

    int start = g_rowptr[gw];
    int end   = start + g_degcnt[gw];
    bool two = (lane < 8);

    float a1 = 0.f, a2 = 0.f;
    for (int k = start; k < end; k++) {
        int2 p = g_csr[k];
        float w = __int_as_float(p.y);
        size_t rb = (size_t)p.x * CC;
        a1 = fmaf(w, __ldg(h3 + rb + lane), a1);
        if (two) a2 = fmaf(w, __ldg(h3 + rb + 32 + lane), a2);
    }

    size_t rb = (size_t)gw * CC;
    float id = g_invdeg[gw];
    float v1 = fmaf(id, h3[rb + lane], a1) + b3[lane];
    float v2 = -INFINITY;
    if (two) v2 = fmaf(id, h3[rb + 32 + lane], a2) + b3[32 + lane];

    float m = fmaxf(v1, v2);
#pragma unroll
    for (int off = 16; off > 0; off >>= 1)
        m = fmaxf(m, __shfl_xor_sync(0xFFFFFFFFu, m, off));

    float s = expf(v1 - m) + (two ? expf(v2 - m) : 0.f);
#pragma unroll
    for (int off = 16; off > 0; off >>= 1)
        s += __shfl_xor_sync(0xFFFFFFFFu, s, off);

    float lse = m + logf(s);
    out[rb + lane] = v1 - lse;
    if (two) out[rb + 32 + lane] = v2 - lse;
}

// ---------------- launch ----------------
extern "C" void kernel_launch(void* const* d_in, const int* in_sizes, int n_in,
                              void* d_out, int out_size)
{
    const float* x   = (const float*)d_in[0];
    const float* W1  = (const float*)d_in[1];
    const float* b1  = (const float*)d_in[2];
    const float* W2  = (const float*)d_in[3];
    const float* b2  = (const float*)d_in[4];
    const float* W3  = (const float*)d_in[5];
    const float* b3  = (const float*)d_in[6];
    const float* g1  = (const float*)d_in[7];
    const float* be1 = (const float*)d_in[8];
    const float* g2  = (const float*)d_in[9];
    const float* be2 = (const float*)d_in[10];
    const int*   ei  = (const int*)d_in[11];
    const int* src = ei;
    const int* dst = ei + EE;
    float* out = (float*)d_out;

    void* p;
    cudaGetSymbolAddress(&p, g_h);
    float* h = (float*)p;
    cudaGetSymbolAddress(&p, g_agg);
    float* agg = (float*)p;
    cudaGetSymbolAddress(&p, g_stats);
    double* stats = (double*)p;
    cudaGetSymbolAddress(&p, g_degcnt);
    int* degcnt = (int*)p;
    cudaGetSymbolAddress(&p, g_cursor);
    int* cursor = (int*)p;

    const int SMEM_MMA = 4 * HH * LDP * 2;            // 139,264 B
    const int SMEM40   = (HH * CC + 8 * 8 * HH) * 4;  // 52 KB
    cudaFuncSetAttribute(gemm128_mma_kernel<false>, cudaFuncAttributeMaxDynamicSharedMemorySize, SMEM_MMA);
    cudaFuncSetAttribute(gemm128_mma_kernel<true>,  cudaFuncAttributeMaxDynamicSharedMemorySize, SMEM_MMA);
    cudaFuncSetAttribute(gemm40_kernel<true>,       cudaFuncAttributeMaxDynamicSharedMemorySize, SMEM40);

    const int MMA_GRID = (NN + 127) / 128;
    const int G40_GRID = (NN + 63) / 64;
    const int AGG_GRID = 1184;

    // degree + CSR build
    cudaMemsetAsync(degcnt, 0, NN * sizeof(int));
    deg_count_kernel<<<(EE + 255) / 256, 256>>>(dst);
    deg_finish_kernel<<<(NN + 255) / 256, 256>>>();
    scan1_kernel<<<SCAN_NB, SCAN_BLK>>>();
    scan2_kernel<<<1, 128>>>();
    scan3_kernel<<<(NN + 255) / 256, 256>>>();
    cudaMemsetAsync(cursor, 0, NN * sizeof(int));
    csr_fill_kernel<<<(EE + 255) / 256, 256>>>(src, dst);

    // layer 1
    gemm128_mma_kernel<false><<<MMA_GRID, 256, SMEM_MMA>>>(x, W1, h, NN);
    cudaMemsetAsync(stats, 0, 2 * HH * sizeof(double));
    aggregate128_kernel<<<AGG_GRID, 256>>>(h, agg, b1);
    stats_final_kernel<<<1, HH>>>(g1, be1);

    // layer 2
    gemm128_mma_kernel<true><<<MMA_GRID, 256, SMEM_MMA>>>(agg, W2, h, NN);
    cudaMemsetAsync(stats, 0, 2 * HH * sizeof(double));
    aggregate128_kernel<<<AGG_GRID, 256>>>(h, agg, b2);
    stats_final_kernel<<<1, HH>>>(g2, be2);

    // layer 3
    gemm40_kernel<true><<<G40_GRID, 256, SMEM40>>>(agg, W3, h, NN);
    aggregate40_softmax_kernel<<<(NN + 7) / 8, 256>>>(h, b3, out);
}

// round 7
// speedup vs baseline: 1.0151x; 1.0151x over previous
#include <cuda_runtime.h>
#include <cuda_bf16.h>
#include <math.h>

#define NN 100000
#define EE 1600000
#define HH 128
#define CC 40
#define BN_EPS 1e-5f
#define SCAN_BLK 1024
#define SCAN_NB ((NN + SCAN_BLK - 1) / SCAN_BLK)

// ---------------- scratch ----------------
__device__ float  g_h[(size_t)NN * HH];
__device__ float  g_agg[(size_t)NN * HH];
__device__ double g_stats[2 * HH];
__device__ float  g_scale[HH];
__device__ float  g_shift[HH];
__device__ int    g_degcnt[NN];
__device__ float  g_dinv[NN];
__device__ float  g_invdeg[NN];
__device__ int    g_rowptr[NN];
__device__ int    g_cursor[NN];
__device__ int    g_blksum[SCAN_NB];
__device__ int2   g_csr[EE];

// ---------------- helpers ----------------
__device__ __forceinline__ void fma4(float4& a, float s, float4 w) {
    a.x = fmaf(s, w.x, a.x);
    a.y = fmaf(s, w.y, a.y);
    a.z = fmaf(s, w.z, a.z);
    a.w = fmaf(s, w.w, a.w);
}

__device__ __forceinline__ float4 bn_relu4(float4 v, float4 sc, float4 sh) {
    float4 r;
    r.x = fmaxf(fmaf(v.x, sc.x, sh.x), 0.f);
    r.y = fmaxf(fmaf(v.y, sc.y, sh.y), 0.f);
    r.z = fmaxf(fmaf(v.z, sc.z, sh.z), 0.f);
    r.w = fmaxf(fmaf(v.w, sc.w, sh.w), 0.f);
    return r;
}

// packed f32x2 ops (Blackwell)
__device__ __forceinline__ unsigned long long pack2(float lo, float hi) {
    unsigned long long d;
    asm("mov.b64 %0, {%1, %2};" : "=l"(d) : "f"(lo), "f"(hi));
    return d;
}

__device__ __forceinline__ void unpack2(unsigned long long v, float& lo, float& hi) {
    asm("mov.b64 {%0, %1}, %2;" : "=f"(lo), "=f"(hi) : "l"(v));
}

__device__ __forceinline__ void ffma2(unsigned long long& d, unsigned long long a,
                                      unsigned long long b) {
    asm("fma.rn.f32x2 %0, %1, %2, %0;" : "+l"(d) : "l"(a), "l"(b));
}

__device__ __forceinline__ float sum2(unsigned long long v) {
    float lo, hi;
    unpack2(v, lo, hi);
    return lo + hi;
}

// ---------------- degree ----------------
__global__ void deg_count_kernel(const int* __restrict__ dst) {
    int e = blockIdx.x * blockDim.x + threadIdx.x;
    if (e < EE) atomicAdd(&g_degcnt[dst[e]], 1);
}

__global__ void deg_finish_kernel() {
    int i = blockIdx.x * blockDim.x + threadIdx.x;
    if (i < NN) {
        float f = (float)(g_degcnt[i] + 1);
        g_dinv[i]   = rsqrtf(f);
        g_invdeg[i] = 1.0f / f;
    }
}

// ---------------- exclusive scan ----------------
__global__ __launch_bounds__(SCAN_BLK) void scan1_kernel() {
    __shared__ int sm[SCAN_BLK];
    int i = blockIdx.x * SCAN_BLK + threadIdx.x;
    int v = (i < NN) ? g_degcnt[i] : 0;
    sm[threadIdx.x] = v;
    __syncthreads();
    for (int off = 1; off < SCAN_BLK; off <<= 1) {
        int t = (threadIdx.x >= off) ? sm[threadIdx.x - off] : 0;
        __syncthreads();
        sm[threadIdx.x] += t;
        __syncthreads();
    }
    if (i < NN) g_rowptr[i] = sm[threadIdx.x] - v;
    if (threadIdx.x == SCAN_BLK - 1) g_blksum[blockIdx.x] = sm[SCAN_BLK - 1];
}

__global__ void scan2_kernel() {
    __shared__ int sm[128];
    int v = (threadIdx.x < SCAN_NB) ? g_blksum[threadIdx.x] : 0;
    sm[threadIdx.x] = v;
    __syncthreads();
    for (int off = 1; off < 128; off <<= 1) {
        int t = (threadIdx.x >= off) ? sm[threadIdx.x - off] : 0;
        __syncthreads();
        sm[threadIdx.x] += t;
        __syncthreads();
    }
    if (threadIdx.x < SCAN_NB) g_blksum[threadIdx.x] = sm[threadIdx.x] - v;
}

__global__ void scan3_kernel() {
    int i = blockIdx.x * blockDim.x + threadIdx.x;
    if (i < NN) g_rowptr[i] += g_blksum[i >> 10];
}

// ---------------- CSR fill ----------------
__global__ void csr_fill_kernel(const int* __restrict__ src,
                                const int* __restrict__ dst) {
    int e = blockIdx.x * blockDim.x + threadIdx.x;
    if (e >= EE) return;
    int s = src[e], d = dst[e];
    int pos = g_rowptr[d] + atomicAdd(&g_cursor[d], 1);
    float w = g_dinv[s] * g_dinv[d];
    g_csr[pos] = make_int2(s, __float_as_int(w));
}

// ---------------- GEMM [n,128]@[128,128], FFMA2-packed SIMT, fused BN+ReLU ----------------
// 256 thr / 8 warps; block tile 64 rows x 128 cols; warp: 8 rows; lane: cols 4l..4l+3.
// smem: Wp float2[64][128] (k-pair interleaved, 64KB) + Xs float4[8][8][32] (32KB) = 96KB.
template<bool BN>
__global__ __launch_bounds__(256, 2) void gemm128_kernel(
    const float* __restrict__ X, const float* __restrict__ W,
    float* __restrict__ Y, int nrows)
{
    extern __shared__ float smem[];
    float* Wp = smem;                         // float2[64][128] as floats
    float4* Xs = (float4*)(smem + 64 * 128 * 2);

    int tid  = threadIdx.x;
    int lane = tid & 31;
    int warp = tid >> 5;

    // stage Wp[k/2][n] = (W[k][n], W[k+1][n])
    for (int i = tid; i < HH * HH; i += 256) {
        int k = i >> 7;
        int n = i & 127;
        Wp[((k >> 1) * 128 + n) * 2 + (k & 1)] = W[i];
    }

    // stage X (fused BN+ReLU), warp-private rows
    float4 sc, sh;
    if (BN) {
        sc = ((const float4*)g_scale)[lane];
        sh = ((const float4*)g_shift)[lane];
    }
    int base = blockIdx.x * 64 + warp * 8;
    const float4* X4 = (const float4*)X;
    float4* Xw = Xs + warp * 8 * 32;
#pragma unroll
    for (int r = 0; r < 8; r++) {
        int row = base + r;
        float4 xv = make_float4(0.f, 0.f, 0.f, 0.f);
        if (row < nrows) xv = X4[(size_t)row * 32 + lane];
        if (BN) xv = bn_relu4(xv, sc, sh);
        Xw[r * 32 + lane] = xv;
    }
    __syncthreads();

    // accumulators: acc[r][j] f32x2 = (k-even partial, k-odd partial)
    unsigned long long acc[8][4];
#pragma unroll
    for (int r = 0; r < 8; r++)
#pragma unroll
        for (int j = 0; j < 4; j++) acc[r][j] = 0ull;

    const float* WpL = Wp + lane * 8;   // lane's 4 float2 cols within a k-pair row

#pragma unroll 4
    for (int k2 = 0; k2 < 64; k2 += 2) {
        // W operands: 4 ull per k-pair (cols j0..j3), 2 LDS.128 each
        longlong2 wA0 = *(const longlong2*)(WpL + (size_t)k2 * 256);
        longlong2 wA1 = *(const longlong2*)(WpL + (size_t)k2 * 256 + 4);
        longlong2 wB0 = *(const longlong2*)(WpL + (size_t)(k2 + 1) * 256);
        longlong2 wB1 = *(const longlong2*)(WpL + (size_t)(k2 + 1) * 256 + 4);
        unsigned long long wa[4], wb[4];
        wa[0] = (unsigned long long)wA0.x;
        wa[1] = (unsigned long long)wA0.y;
        wa[2] = (unsigned long long)wA1.x;
        wa[3] = (unsigned long long)wA1.y;
        wb[0] = (unsigned long long)wB0.x;
        wb[1] = (unsigned long long)wB0.y;
        wb[2] = (unsigned long long)wB1.x;
        wb[3] = (unsigned long long)wB1.y;

#pragma unroll
        for (int r = 0; r < 8; r++) {
            float4 xq = Xw[r * 32 + (k2 >> 1)];   // k = 2*k2 .. 2*k2+3
            unsigned long long xa = pack2(xq.x, xq.y);
            unsigned long long xb = pack2(xq.z, xq.w);
            ffma2(acc[r][0], xa, wa[0]);
            ffma2(acc[r][1], xa, wa[1]);
            ffma2(acc[r][2], xa, wa[2]);
            ffma2(acc[r][3], xa, wa[3]);
            ffma2(acc[r][0], xb, wb[0]);
            ffma2(acc[r][1], xb, wb[1]);
            ffma2(acc[r][2], xb, wb[2]);
            ffma2(acc[r][3], xb, wb[3]);
        }
    }

#pragma unroll
    for (int r = 0; r < 8; r++) {
        int row = base + r;
        if (row < nrows) {
            float4 o;
            o.x = sum2(acc[r][0]);
            o.y = sum2(acc[r][1]);
            o.z = sum2(acc[r][2]);
            o.w = sum2(acc[r][3]);
            ((float4*)Y)[(size_t)row * 32 + lane] = o;
        }
    }
}

// ---------------- GEMM [n,128]@[128,40], FFMA2-packed, fused BN+ReLU ----------------
// lane col j1=lane; lane<8 also col 32+lane. smem: Wp40 20KB + Xs 32KB.
template<bool BN>
__global__ __launch_bounds__(256, 2) void gemm40_kernel(
    const float* __restrict__ X, const float* __restrict__ W,
    float* __restrict__ Y, int nrows)
{
    extern __shared__ float smem[];
    float* Wp = smem;                          // float2[64][40] as floats
    float4* Xs = (float4*)(smem + 64 * CC * 2);

    int tid  = threadIdx.x;
    int lane = tid & 31;
    int warp = tid >> 5;

    for (int i = tid; i < HH * CC; i += 256) {
        int k = i / CC;
        int n = i - k * CC;
        Wp[((k >> 1) * CC + n) * 2 + (k & 1)] = W[i];
    }

    float4 sc, sh;
    if (BN) {
        sc = ((const float4*)g_scale)[lane];
        sh = ((const float4*)g_shift)[lane];
    }
    int base = blockIdx.x * 64 + warp * 8;
    const float4* X4 = (const float4*)X;
    float4* Xw = Xs + warp * 8 * 32;
#pragma unroll
    for (int r = 0; r < 8; r++) {
        int row = base + r;
        float4 xv = make_float4(0.f, 0.f, 0.f, 0.f);
        if (row < nrows) xv = X4[(size_t)row * 32 + lane];
        if (BN) xv = bn_relu4(xv, sc, sh);
        Xw[r * 32 + lane] = xv;
    }
    __syncthreads();

    unsigned long long acca[8], accb[8];
#pragma unroll
    for (int r = 0; r < 8; r++) {
        acca[r] = 0ull;
        accb[r] = 0ull;
    }
    bool two = (lane < 8);

#pragma unroll 4
    for (int k2 = 0; k2 < 64; k2 += 2) {
        unsigned long long waA = *(const unsigned long long*)(Wp + ((size_t)k2 * CC + lane) * 2);
        unsigned long long waB = *(const unsigned long long*)(Wp + ((size_t)(k2 + 1) * CC + lane) * 2);
        unsigned long long wbA = 0ull, wbB = 0ull;
        if (two) {
            wbA = *(const unsigned long long*)(Wp + ((size_t)k2 * CC + 32 + lane) * 2);
            wbB = *(const unsigned long long*)(Wp + ((size_t)(k2 + 1) * CC + 32 + lane) * 2);
        }
#pragma unroll
        for (int r = 0; r < 8; r++) {
            float4 xq = Xw[r * 32 + (k2 >> 1)];
            unsigned long long xa = pack2(xq.x, xq.y);
            unsigned long long xb = pack2(xq.z, xq.w);
            ffma2(acca[r], xa, waA);
            ffma2(acca[r], xb, waB);
            ffma2(accb[r], xa, wbA);
            ffma2(accb[r], xb, wbB);
        }
    }

#pragma unroll
    for (int r = 0; r < 8; r++) {
        int row = base + r;
        if (row < nrows) {
            Y[(size_t)row * CC + lane] = sum2(acca[r]);
            if (two) Y[(size_t)row * CC + 32 + lane] = sum2(accb[r]);
        }
    }
}

// ---------------- fused CSR aggregation + self-loop + bias + BN stats ----------------
__global__ __launch_bounds__(256) void aggregate128_kernel(
    const float* __restrict__ h, float* __restrict__ agg,
    const float* __restrict__ bias)
{
    __shared__ float ssum[8 * HH];
    __shared__ float ssq[8 * HH];

    int lane = threadIdx.x & 31;
    int warp = threadIdx.x >> 5;
    int gw = blockIdx.x * 8 + warp;
    int nwarps = gridDim.x * 8;

    float4 bb = ((const float4*)bias)[lane];
    float4 ps  = make_float4(0.f, 0.f, 0.f, 0.f);
    float4 ps2 = make_float4(0.f, 0.f, 0.f, 0.f);

    const float4* h4 = (const float4*)h;

    for (int i = gw; i < NN; i += nwarps) {
        int start = g_rowptr[i];
        int end   = start + g_degcnt[i];
        float4 acc = make_float4(0.f, 0.f, 0.f, 0.f);

        int k = start;
        for (; k + 1 < end; k += 2) {
            int2 p0 = g_csr[k];
            int2 p1 = g_csr[k + 1];
            float4 v0 = __ldg(h4 + (size_t)p0.x * 32 + lane);
            float4 v1 = __ldg(h4 + (size_t)p1.x * 32 + lane);
            fma4(acc, __int_as_float(p0.y), v0);
            fma4(acc, __int_as_float(p1.y), v1);
        }
        if (k < end) {
            int2 p0 = g_csr[k];
            float4 v0 = __ldg(h4 + (size_t)p0.x * 32 + lane);
            fma4(acc, __int_as_float(p0.y), v0);
        }

        float4 hv = h4[(size_t)i * 32 + lane];
        float id = g_invdeg[i];
        acc.x = fmaf(id, hv.x, acc.x) + bb.x;
        acc.y = fmaf(id, hv.y, acc.y) + bb.y;
        acc.z = fmaf(id, hv.z, acc.z) + bb.z;
        acc.w = fmaf(id, hv.w, acc.w) + bb.w;
        ((float4*)agg)[(size_t)i * 32 + lane] = acc;

        ps.x += acc.x;
        ps.y += acc.y;
        ps.z += acc.z;
        ps.w += acc.w;
        ps2.x = fmaf(acc.x, acc.x, ps2.x);
        ps2.y = fmaf(acc.y, acc.y, ps2.y);
        ps2.z = fmaf(acc.z, acc.z, ps2.z);
        ps2.w = fmaf(acc.w, acc.w, ps2.w);
    }

    ((float4*)(ssum + warp * HH))[lane] = ps;
    ((float4*)(ssq  + warp * HH))[lane] = ps2;
    __syncthreads();
    if (threadIdx.x < HH) {
        int j = threadIdx.x;
        float ts = 0.f, ts2 = 0.f;
#pragma unroll
        for (int w = 0; w < 8; w++) {
            ts  += ssum[w * HH + j];
            ts2 += ssq[w * HH + j];
        }
        atomicAdd(&g_stats[j],      (double)ts);
        atomicAdd(&g_stats[HH + j], (double)ts2);
    }
}

__global__ void stats_final_kernel(const float* __restrict__ g,
                                   const float* __restrict__ be)
{
    int j = threadIdx.x;
    double mu  = g_stats[j] / (double)NN;
    double var = g_stats[HH + j] / (double)NN - mu * mu;
    float rs = rsqrtf((float)var + BN_EPS);
    float sc = g[j] * rs;
    g_scale[j] = sc;
    g_shift[j] = be[j] - (float)mu * sc;
}

// ---------------- layer-3: fused aggregation + bias + log_softmax ----------------
__global__ __launch_bounds__(256) void aggregate40_softmax_kernel(
    const float* __restrict__ h3, const float* __restrict__ b3,
    float* __restrict__ out)
{
    int lane = threadIdx.x & 31;
    int warp = threadIdx.x >> 5;
    int gw = blockIdx.x * 8 + warp;
    if (gw >= NN) return;

    int start = g_rowptr[gw];
    int end   = start + g_degcnt[gw];
    bool two = (lane < 8);

    float a1 = 0.f, a2 = 0.f;
    for (int k = start; k < end; k++) {
        int2 p = g_csr[k];
        float w = __int_as_float(p.y);
        size_t rb = (size_t)p.x * CC;
        a1 = fmaf(w, __ldg(h3 + rb + lane), a1);
        if (two) a2 = fmaf(w, __ldg(h3 + rb + 32 + lane), a2);
    }

    size_t rb = (size_t)gw * CC;
    float id = g_invdeg[gw];
    float v1 = fmaf(id, h3[rb + lane], a1) + b3[lane];
    float v2 = -INFINITY;
    if (two) v2 = fmaf(id, h3[rb + 32 + lane], a2) + b3[32 + lane];

    float m = fmaxf(v1, v2);
#pragma unroll
    for (int off = 16; off > 0; off >>= 1)
        m = fmaxf(m, __shfl_xor_sync(0xFFFFFFFFu, m, off));

    float s = expf(v1 - m) + (two ? expf(v2 - m) : 0.f);
#pragma unroll
    for (int off = 16; off > 0; off >>= 1)
        s += __shfl_xor_sync(0xFFFFFFFFu, s, off);

    float lse = m + logf(s);
    out[rb + lane] = v1 - lse;
    if (two) out[rb + 32 + lane] = v2 - lse;
}

// ---------------- launch ----------------
extern "C" void kernel_launch(void* const* d_in, const int* in_sizes, int n_in,
                              void* d_out, int out_size)
{
    const float* x   = (const float*)d_in[0];
    const float* W1  = (const float*)d_in[1];
    const float* b1  = (const float*)d_in[2];
    const float* W2  = (const float*)d_in[3];
    const float* b2  = (const float*)d_in[4];
    const float* W3  = (const float*)d_in[5];
    const float* b3  = (const float*)d_in[6];
    const float* g1  = (const float*)d_in[7];
    const float* be1 = (const float*)d_in[8];
    const float* g2  = (const float*)d_in[9];
    const float* be2 = (const float*)d_in[10];
    const int*   ei  = (const int*)d_in[11];
    const int* src = ei;
    const int* dst = ei + EE;
    float* out = (float*)d_out;

    void* p;
    cudaGetSymbolAddress(&p, g_h);
    float* h = (float*)p;
    cudaGetSymbolAddress(&p, g_agg);
    float* agg = (float*)p;
    cudaGetSymbolAddress(&p, g_stats);
    double* stats = (double*)p;
    cudaGetSymbolAddress(&p, g_degcnt);
    int* degcnt = (int*)p;
    cudaGetSymbolAddress(&p, g_cursor);
    int* cursor = (int*)p;

    const int SMEM128 = (64 * 128 * 2 + 8 * 8 * 128) * 4;  // 64KB + 32KB = 98304
    const int SMEM40  = (64 * CC * 2 + 8 * 8 * 128) * 4;   // 20KB + 32KB = 53248
    cudaFuncSetAttribute(gemm128_kernel<false>, cudaFuncAttributeMaxDynamicSharedMemorySize, SMEM128);
    cudaFuncSetAttribute(gemm128_kernel<true>,  cudaFuncAttributeMaxDynamicSharedMemorySize, SMEM128);
    cudaFuncSetAttribute(gemm40_kernel<true>,   cudaFuncAttributeMaxDynamicSharedMemorySize, SMEM40);

    const int GEMM_GRID = (NN + 63) / 64;
    const int AGG_GRID  = 1184;

    // degree + CSR build
    cudaMemsetAsync(degcnt, 0, NN * sizeof(int));
    deg_count_kernel<<<(EE + 255) / 256, 256>>>(dst);
    deg_finish_kernel<<<(NN + 255) / 256, 256>>>();
    scan1_kernel<<<SCAN_NB, SCAN_BLK>>>();
    scan2_kernel<<<1, 128>>>();
    scan3_kernel<<<(NN + 255) / 256, 256>>>();
    cudaMemsetAsync(cursor, 0, NN * sizeof(int));
    csr_fill_kernel<<<(EE + 255) / 256, 256>>>(src, dst);

    // layer 1
    gemm128_kernel<false><<<GEMM_GRID, 256, SMEM128>>>(x, W1, h, NN);
    cudaMemsetAsync(stats, 0, 2 * HH * sizeof(double));
    aggregate128_kernel<<<AGG_GRID, 256>>>(h, agg, b1);
    stats_final_kernel<<<1, HH>>>(g1, be1);

    // layer 2
    gemm128_kernel<true><<<GEMM_GRID, 256, SMEM128>>>(agg, W2, h, NN);
    cudaMemsetAsync(stats, 0, 2 * HH * sizeof(double));
    aggregate128_kernel<<<AGG_GRID, 256>>>(h, agg, b2);
    stats_final_kernel<<<1, HH>>>(g2, be2);

    // layer 3
    gemm40_kernel<true><<<GEMM_GRID, 256, SMEM40>>>(agg, W3, h, NN);
    aggregate40_softmax_kernel<<<(NN + 7) / 8, 256>>>(h, b3, out);
}

// round 8
// speedup vs baseline: 1.1165x; 1.0999x over previous
#include <cuda_runtime.h>
#include <cuda_fp16.h>
#include <math.h>

#define NN 100000
#define EE 1600000
#define HH 128
#define CC 40
#define BN_EPS 1e-5f
#define SCAN_BLK 1024
#define SCAN_NB ((NN + SCAN_BLK - 1) / SCAN_BLK)   // 98

// ---------------- scratch ----------------
__device__ float  g_h[(size_t)NN * HH];       // fp32 GEMM output (self-loop source)
__device__ __half g_h16[(size_t)NN * HH];     // fp16 mirror for gathers (layer3 reuses NN*40)
__device__ float  g_agg[(size_t)NN * HH];
__device__ double g_stats[2 * HH];
__device__ float  g_scale[HH];
__device__ float  g_shift[HH];
__device__ int    g_degcnt[NN];
__device__ float  g_dinv[NN];
__device__ float  g_invdeg[NN];
__device__ int    g_rowptr[NN];
__device__ int    g_cursor[NN];
__device__ int    g_blksum[SCAN_NB];
__device__ int2   g_csr[EE];

// ---------------- helpers ----------------
__device__ __forceinline__ void fma4(float4& a, float s, float4 w) {
    a.x = fmaf(s, w.x, a.x);
    a.y = fmaf(s, w.y, a.y);
    a.z = fmaf(s, w.z, a.z);
    a.w = fmaf(s, w.w, a.w);
}

__device__ __forceinline__ float4 bn_relu4(float4 v, float4 sc, float4 sh) {
    float4 r;
    r.x = fmaxf(fmaf(v.x, sc.x, sh.x), 0.f);
    r.y = fmaxf(fmaf(v.y, sc.y, sh.y), 0.f);
    r.z = fmaxf(fmaf(v.z, sc.z, sh.z), 0.f);
    r.w = fmaxf(fmaf(v.w, sc.w, sh.w), 0.f);
    return r;
}

// fma acc += w * (4 halves packed in uint2)
__device__ __forceinline__ void fma4_h(float4& a, float w, uint2 v) {
    __half2 h01 = *reinterpret_cast<__half2*>(&v.x);
    __half2 h23 = *reinterpret_cast<__half2*>(&v.y);
    float2 f01 = __half22float2(h01);
    float2 f23 = __half22float2(h23);
    a.x = fmaf(w, f01.x, a.x);
    a.y = fmaf(w, f01.y, a.y);
    a.z = fmaf(w, f23.x, a.z);
    a.w = fmaf(w, f23.y, a.w);
}

// ---------------- degree ----------------
__global__ void deg_count_kernel(const int* __restrict__ dst) {
    int e = blockIdx.x * blockDim.x + threadIdx.x;
    if (e < EE) atomicAdd(&g_degcnt[dst[e]], 1);
}

// ---------------- scan1: block-local exclusive scan + degree finish ----------------
__global__ __launch_bounds__(SCAN_BLK) void scan1_kernel() {
    __shared__ int sm[SCAN_BLK];
    int i = blockIdx.x * SCAN_BLK + threadIdx.x;
    int v = (i < NN) ? g_degcnt[i] : 0;
    sm[threadIdx.x] = v;
    __syncthreads();
    for (int off = 1; off < SCAN_BLK; off <<= 1) {
        int t = (threadIdx.x >= off) ? sm[threadIdx.x - off] : 0;
        __syncthreads();
        sm[threadIdx.x] += t;
        __syncthreads();
    }
    if (i < NN) {
        g_rowptr[i] = sm[threadIdx.x] - v;   // exclusive within block
        float f = (float)(v + 1);
        g_dinv[i]   = rsqrtf(f);
        g_invdeg[i] = 1.0f / f;
    }
    if (threadIdx.x == SCAN_BLK - 1) g_blksum[blockIdx.x] = sm[SCAN_BLK - 1];
}

// ---------------- scan23: add block-prefix (computed in-block) + init cursor ----------------
__global__ __launch_bounds__(256) void scan23_kernel() {
    __shared__ int sm[256];
    int t = threadIdx.x;
    int v = (t < SCAN_NB) ? g_blksum[t] : 0;
    sm[t] = v;
    __syncthreads();
    for (int off = 1; off < 256; off <<= 1) {
        int u = (t >= off) ? sm[t - off] : 0;
        __syncthreads();
        sm[t] += u;
        __syncthreads();
    }
    // exclusive prefix for block b = sm[b] - blksum[b]
    int i = blockIdx.x * 256 + t;
    if (i < NN) {
        int b = i >> 10;
        int pref = sm[b] - g_blksum[b];
        int rp = g_rowptr[i] + pref;
        g_rowptr[i] = rp;
        g_cursor[i] = rp;   // cursor starts at row start
    }
}

// ---------------- CSR fill ----------------
__global__ void csr_fill_kernel(const int* __restrict__ src,
                                const int* __restrict__ dst) {
    int e = blockIdx.x * blockDim.x + threadIdx.x;
    if (e >= EE) return;
    int s = src[e], d = dst[e];
    int pos = atomicAdd(&g_cursor[d], 1);
    float w = g_dinv[s] * g_dinv[d];
    g_csr[pos] = make_int2(s, __float_as_int(w));
}

// ---------------- GEMM [n,128]@[128,128] (R3 fma4 version) + h16 mirror ----------------
// 256 thr / 8 warps; block tile 64x128; warp: 8 rows. smem 96KB.
template<bool BN>
__global__ __launch_bounds__(256) void gemm128_kernel(
    const float* __restrict__ X, const float* __restrict__ W,
    float* __restrict__ Y, __half* __restrict__ Y16, int nrows)
{
    extern __shared__ float smem[];
    float4* Ws = (float4*)smem;               // [128][32] float4
    float4* Xs = (float4*)smem + HH * 32;     // [8][8][32] float4

    int tid  = threadIdx.x;
    int lane = tid & 31, warp = tid >> 5;

    const float4* W4 = (const float4*)W;
    for (int i = tid; i < HH * 32; i += 256) Ws[i] = W4[i];
    __syncthreads();

    float4 sc, sh;
    if (BN) { sc = ((const float4*)g_scale)[lane]; sh = ((const float4*)g_shift)[lane]; }

    int base = blockIdx.x * 64 + warp * 8;
    const float4* X4 = (const float4*)X;
    float4* Xw = Xs + warp * 8 * 32;

#pragma unroll
    for (int r = 0; r < 8; r++) {
        int row = base + r;
        float4 xv = make_float4(0.f, 0.f, 0.f, 0.f);
        if (row < nrows) xv = X4[(size_t)row * 32 + lane];
        if (BN) xv = bn_relu4(xv, sc, sh);
        Xw[r * 32 + lane] = xv;
    }
    __syncwarp();

    float4 acc[8];
#pragma unroll
    for (int r = 0; r < 8; r++) acc[r] = make_float4(0.f, 0.f, 0.f, 0.f);

#pragma unroll 4
    for (int k0 = 0; k0 < 32; k0++) {
        float4 w0 = Ws[(4 * k0 + 0) * 32 + lane];
        float4 w1 = Ws[(4 * k0 + 1) * 32 + lane];
        float4 w2 = Ws[(4 * k0 + 2) * 32 + lane];
        float4 w3 = Ws[(4 * k0 + 3) * 32 + lane];
#pragma unroll
        for (int r = 0; r < 8; r++) {
            float4 xv = Xw[r * 32 + k0];
            fma4(acc[r], xv.x, w0);
            fma4(acc[r], xv.y, w1);
            fma4(acc[r], xv.z, w2);
            fma4(acc[r], xv.w, w3);
        }
    }

#pragma unroll
    for (int r = 0; r < 8; r++) {
        int row = base + r;
        if (row < nrows) {
            ((float4*)Y)[(size_t)row * 32 + lane] = acc[r];
            __half2 p0 = __floats2half2_rn(acc[r].x, acc[r].y);
            __half2 p1 = __floats2half2_rn(acc[r].z, acc[r].w);
            uint2 u;
            u.x = *reinterpret_cast<unsigned*>(&p0);
            u.y = *reinterpret_cast<unsigned*>(&p1);
            ((uint2*)Y16)[(size_t)row * 32 + lane] = u;
        }
    }
}

// ---------------- GEMM [n,128]@[128,40] (R3 version) + h16 mirror ----------------
template<bool BN>
__global__ __launch_bounds__(256) void gemm40_kernel(
    const float* __restrict__ X, const float* __restrict__ W,
    float* __restrict__ Y, __half* __restrict__ Y16, int nrows)
{
    extern __shared__ float smem[];
    float*  Ws = smem;                        // [128][40]
    float4* Xs = (float4*)(smem + HH * CC);

    int tid  = threadIdx.x;
    int lane = tid & 31, warp = tid >> 5;

    for (int i = tid; i < HH * CC; i += 256) Ws[i] = W[i];
    __syncthreads();

    float4 sc, sh;
    if (BN) { sc = ((const float4*)g_scale)[lane]; sh = ((const float4*)g_shift)[lane]; }

    int base = blockIdx.x * 64 + warp * 8;
    const float4* X4 = (const float4*)X;
    float4* Xw = Xs + warp * 8 * 32;

#pragma unroll
    for (int r = 0; r < 8; r++) {
        int row = base + r;
        float4 xv = make_float4(0.f, 0.f, 0.f, 0.f);
        if (row < nrows) xv = X4[(size_t)row * 32 + lane];
        if (BN) xv = bn_relu4(xv, sc, sh);
        Xw[r * 32 + lane] = xv;
    }
    __syncwarp();

    float acca[8], accb[8];
#pragma unroll
    for (int r = 0; r < 8; r++) { acca[r] = 0.f; accb[r] = 0.f; }

    bool two = (lane < 8);

#pragma unroll 4
    for (int k0 = 0; k0 < 32; k0++) {
        float wa[4], wb[4];
#pragma unroll
        for (int j = 0; j < 4; j++) {
            wa[j] = Ws[(4 * k0 + j) * CC + lane];
            wb[j] = two ? Ws[(4 * k0 + j) * CC + 32 + lane] : 0.f;
        }
#pragma unroll
        for (int r = 0; r < 8; r++) {
            float4 xv = Xw[r * 32 + k0];
            acca[r] = fmaf(xv.x, wa[0], acca[r]);
            acca[r] = fmaf(xv.y, wa[1], acca[r]);
            acca[r] = fmaf(xv.z, wa[2], acca[r]);
            acca[r] = fmaf(xv.w, wa[3], acca[r]);
            accb[r] = fmaf(xv.x, wb[0], accb[r]);
            accb[r] = fmaf(xv.y, wb[1], accb[r]);
            accb[r] = fmaf(xv.z, wb[2], accb[r]);
            accb[r] = fmaf(xv.w, wb[3], accb[r]);
        }
    }

#pragma unroll
    for (int r = 0; r < 8; r++) {
        int row = base + r;
        if (row < nrows) {
            Y[(size_t)row * CC + lane] = acca[r];
            Y16[(size_t)row * CC + lane] = __float2half_rn(acca[r]);
            if (two) {
                Y[(size_t)row * CC + 32 + lane] = accb[r];
                Y16[(size_t)row * CC + 32 + lane] = __float2half_rn(accb[r]);
            }
        }
    }
}

// ---------------- fused CSR aggregation (fp16 gather) + self-loop + bias + BN stats ----------------
__global__ __launch_bounds__(256) void aggregate128_kernel(
    const float* __restrict__ h, const __half* __restrict__ h16,
    float* __restrict__ agg, const float* __restrict__ bias)
{
    __shared__ float ssum[8 * HH];
    __shared__ float ssq[8 * HH];

    int lane = threadIdx.x & 31;
    int warp = threadIdx.x >> 5;
    int gw = blockIdx.x * 8 + warp;
    int nwarps = gridDim.x * 8;

    float4 bb = ((const float4*)bias)[lane];
    float4 ps  = make_float4(0.f, 0.f, 0.f, 0.f);
    float4 ps2 = make_float4(0.f, 0.f, 0.f, 0.f);

    const float4* h4   = (const float4*)h;
    const uint2*  h16v = (const uint2*)h16;

    for (int i = gw; i < NN; i += nwarps) {
        int start = g_rowptr[i];
        int end   = start + g_degcnt[i];
        float4 acc = make_float4(0.f, 0.f, 0.f, 0.f);

        int k = start;
        for (; k + 1 < end; k += 2) {
            int2 p0 = g_csr[k];
            int2 p1 = g_csr[k + 1];
            uint2 v0 = __ldg(h16v + (size_t)p0.x * 32 + lane);
            uint2 v1 = __ldg(h16v + (size_t)p1.x * 32 + lane);
            fma4_h(acc, __int_as_float(p0.y), v0);
            fma4_h(acc, __int_as_float(p1.y), v1);
        }
        if (k < end) {
            int2 p0 = g_csr[k];
            uint2 v0 = __ldg(h16v + (size_t)p0.x * 32 + lane);
            fma4_h(acc, __int_as_float(p0.y), v0);
        }

        float4 hv = h4[(size_t)i * 32 + lane];
        float id = g_invdeg[i];
        acc.x = fmaf(id, hv.x, acc.x) + bb.x;
        acc.y = fmaf(id, hv.y, acc.y) + bb.y;
        acc.z = fmaf(id, hv.z, acc.z) + bb.z;
        acc.w = fmaf(id, hv.w, acc.w) + bb.w;
        ((float4*)agg)[(size_t)i * 32 + lane] = acc;

        ps.x += acc.x;
        ps.y += acc.y;
        ps.z += acc.z;
        ps.w += acc.w;
        ps2.x = fmaf(acc.x, acc.x, ps2.x);
        ps2.y = fmaf(acc.y, acc.y, ps2.y);
        ps2.z = fmaf(acc.z, acc.z, ps2.z);
        ps2.w = fmaf(acc.w, acc.w, ps2.w);
    }

    ((float4*)(ssum + warp * HH))[lane] = ps;
    ((float4*)(ssq  + warp * HH))[lane] = ps2;
    __syncthreads();
    if (threadIdx.x < HH) {
        int j = threadIdx.x;
        float ts = 0.f, ts2 = 0.f;
#pragma unroll
        for (int w = 0; w < 8; w++) {
            ts  += ssum[w * HH + j];
            ts2 += ssq[w * HH + j];
        }
        atomicAdd(&g_stats[j],      (double)ts);
        atomicAdd(&g_stats[HH + j], (double)ts2);
    }
}

// stats -> scale/shift, then zero stats for the next layer / next replay
__global__ void stats_final_kernel(const float* __restrict__ g,
                                   const float* __restrict__ be)
{
    int j = threadIdx.x;
    double mu  = g_stats[j] / (double)NN;
    double var = g_stats[HH + j] / (double)NN - mu * mu;
    float rs = rsqrtf((float)var + BN_EPS);
    float sc = g[j] * rs;
    g_scale[j] = sc;
    g_shift[j] = be[j] - (float)mu * sc;
    g_stats[j] = 0.0;
    g_stats[HH + j] = 0.0;
}

// ---------------- layer-3: fused fp16-gather aggregation + bias + log_softmax ----------------
// warp per node; lane l<20 handles cols 2l, 2l+1.
__global__ __launch_bounds__(256) void aggregate40_softmax_kernel(
    const float* __restrict__ h3, const __half* __restrict__ h316,
    const float* __restrict__ b3, float* __restrict__ out)
{
    int lane = threadIdx.x & 31;
    int warp = threadIdx.x >> 5;
    int gw = blockIdx.x * 8 + warp;
    if (gw >= NN) return;

    int start = g_rowptr[gw];
    int end   = start + g_degcnt[gw];
    bool act = (lane < 20);

    const unsigned* h16u = (const unsigned*)h316;

    float a0 = 0.f, a1 = 0.f;
    for (int k = start; k < end; k++) {
        int2 p = g_csr[k];
        float w = __int_as_float(p.y);
        if (act) {
            unsigned v = __ldg(h16u + (size_t)p.x * 20 + lane);
            __half2 hp = *reinterpret_cast<__half2*>(&v);
            float2 f = __half22float2(hp);
            a0 = fmaf(w, f.x, a0);
            a1 = fmaf(w, f.y, a1);
        }
    }

    size_t rb = (size_t)gw * CC;
    float id = g_invdeg[gw];
    float v0 = -INFINITY, v1 = -INFINITY;
    if (act) {
        v0 = fmaf(id, h3[rb + 2 * lane],     a0) + b3[2 * lane];
        v1 = fmaf(id, h3[rb + 2 * lane + 1], a1) + b3[2 * lane + 1];
    }

    float m = fmaxf(v0, v1);
#pragma unroll
    for (int off = 16; off > 0; off >>= 1)
        m = fmaxf(m, __shfl_xor_sync(0xFFFFFFFFu, m, off));

    float s = act ? (expf(v0 - m) + expf(v1 - m)) : 0.f;
#pragma unroll
    for (int off = 16; off > 0; off >>= 1)
        s += __shfl_xor_sync(0xFFFFFFFFu, s, off);

    float lse = m + logf(s);
    if (act) {
        out[rb + 2 * lane]     = v0 - lse;
        out[rb + 2 * lane + 1] = v1 - lse;
    }
}

// ---------------- launch ----------------
extern "C" void kernel_launch(void* const* d_in, const int* in_sizes, int n_in,
                              void* d_out, int out_size)
{
    const float* x   = (const float*)d_in[0];
    const float* W1  = (const float*)d_in[1];
    const float* b1  = (const float*)d_in[2];
    const float* W2  = (const float*)d_in[3];
    const float* b2  = (const float*)d_in[4];
    const float* W3  = (const float*)d_in[5];
    const float* b3  = (const float*)d_in[6];
    const float* g1  = (const float*)d_in[7];
    const float* be1 = (const float*)d_in[8];
    const float* g2  = (const float*)d_in[9];
    const float* be2 = (const float*)d_in[10];
    const int*   ei  = (const int*)d_in[11];
    const int* src = ei;
    const int* dst = ei + EE;
    float* out = (float*)d_out;

    void* p;
    cudaGetSymbolAddress(&p, g_h);
    float* h = (float*)p;
    cudaGetSymbolAddress(&p, g_h16);
    __half* h16 = (__half*)p;
    cudaGetSymbolAddress(&p, g_agg);
    float* agg = (float*)p;
    cudaGetSymbolAddress(&p, g_degcnt);
    int* degcnt = (int*)p;

    const int SMEM128 = (HH * HH + 8 * 8 * HH) * 4;   // 96 KB
    const int SMEM40  = (HH * CC + 8 * 8 * HH) * 4;   // 52 KB
    cudaFuncSetAttribute(gemm128_kernel<false>, cudaFuncAttributeMaxDynamicSharedMemorySize, SMEM128);
    cudaFuncSetAttribute(gemm128_kernel<true>,  cudaFuncAttributeMaxDynamicSharedMemorySize, SMEM128);
    cudaFuncSetAttribute(gemm40_kernel<true>,   cudaFuncAttributeMaxDynamicSharedMemorySize, SMEM40);

    const int GEMM_GRID = (NN + 63) / 64;
    const int AGG_GRID  = 1184;

    // ---- degree + CSR build ----
    cudaMemsetAsync(degcnt, 0, NN * sizeof(int));
    deg_count_kernel<<<(EE + 255) / 256, 256>>>(dst);
    scan1_kernel<<<SCAN_NB, SCAN_BLK>>>();
    scan23_kernel<<<(NN + 255) / 256, 256>>>();
    csr_fill_kernel<<<(EE + 255) / 256, 256>>>(src, dst);

    // ---- layer 1 ----
    gemm128_kernel<false><<<GEMM_GRID, 256, SMEM128>>>(x, W1, h, h16, NN);
    aggregate128_kernel<<<AGG_GRID, 256>>>(h, h16, agg, b1);
    stats_final_kernel<<<1, HH>>>(g1, be1);

    // ---- layer 2 ----
    gemm128_kernel<true><<<GEMM_GRID, 256, SMEM128>>>(agg, W2, h, h16, NN);
    aggregate128_kernel<<<AGG_GRID, 256>>>(h, h16, agg, b2);
    stats_final_kernel<<<1, HH>>>(g2, be2);

    // ---- layer 3 ----
    gemm40_kernel<true><<<GEMM_GRID, 256, SMEM40>>>(agg, W3, h, h16, NN);
    aggregate40_softmax_kernel<<<(NN + 7) / 8, 256>>>(h, h16, b3, out);
}